// round 2
// baseline (speedup 1.0000x reference)
#include <cuda_runtime.h>
#include <cuda_bf16.h>
#include <cstdint>

// Grid_nd_sample: bilinear interpolation gather.
// in_tensor: (B=16, H=128, W=128, C=256) fp32
// indices:   (B=16, P=8192, 2) fp32  -- coord0 = H axis (mu_x), coord1 = W axis (mu_y)
// out:       (B, P, C) fp32
//
// Mapping: one point -> 64 float4 chunks (C=256 fp32 = 64 float4).
// Thread i: chunk = i & 63, point = i >> 6. All 32 lanes of a warp share the
// same point (chunks 0-31 or 32-63), so the index load broadcasts and the 4
// gathered rows are fully coalesced 128B accesses.

static constexpr int B = 16;
static constexpr int H = 128;
static constexpr int W = 128;
static constexpr int C = 256;
static constexpr int P = 8192;
static constexpr int CHUNKS = C / 4;            // 64 float4 per row
static constexpr long long TOTAL = (long long)B * P * CHUNKS;  // 8,388,608 threads

__global__ __launch_bounds__(256, 8)
void grid_nd_sample_kernel(const float* __restrict__ in_tensor,
                           const float2* __restrict__ indices,
                           float4* __restrict__ out)
{
    unsigned int i = blockIdx.x * blockDim.x + threadIdx.x;   // < TOTAL (fits u32)
    unsigned int chunk = i & (CHUNKS - 1);
    unsigned int pidx  = i >> 6;          // b*P + p
    unsigned int b     = pidx >> 13;      // P = 8192 = 2^13

    // Broadcast load of the point's (h, w) coordinates.
    float2 ind = __ldg(&indices[pidx]);

    float fh = floorf(ind.x);
    float fw = floorf(ind.y);
    int h0 = (int)fh;
    int w0 = (int)fw;
    int h1 = (int)ceilf(ind.x);
    int w1 = (int)ceilf(ind.y);
    float mu_h = ind.x - fh;              // weight along H (ref's mu_x)
    float mu_w = ind.y - fw;              // weight along W (ref's mu_y)

    // Row base offsets in float4 units: ((b*H + h)*W + w) * C / 4
    const float4* base = (const float4*)in_tensor;
    unsigned int boff = b * (H * W * CHUNKS);
    unsigned int r00 = boff + (h0 * W + w0) * CHUNKS + chunk;
    unsigned int r10 = boff + (h1 * W + w0) * CHUNKS + chunk;
    unsigned int r01 = boff + (h0 * W + w1) * CHUNKS + chunk;
    unsigned int r11 = boff + (h1 * W + w1) * CHUNKS + chunk;

    float4 p1 = __ldg(&base[r00]);
    float4 p2 = __ldg(&base[r10]);
    float4 p3 = __ldg(&base[r01]);
    float4 p4 = __ldg(&base[r11]);

    // p12 = p1 + mu_h*(p2-p1); p34 = p3 + mu_h*(p4-p3); out = p12 + mu_w*(p34-p12)
    float4 o;
    {
        float a = fmaf(mu_h, p2.x - p1.x, p1.x);
        float c2 = fmaf(mu_h, p4.x - p3.x, p3.x);
        o.x = fmaf(mu_w, c2 - a, a);
    }
    {
        float a = fmaf(mu_h, p2.y - p1.y, p1.y);
        float c2 = fmaf(mu_h, p4.y - p3.y, p3.y);
        o.y = fmaf(mu_w, c2 - a, a);
    }
    {
        float a = fmaf(mu_h, p2.z - p1.z, p1.z);
        float c2 = fmaf(mu_h, p4.z - p3.z, p3.z);
        o.z = fmaf(mu_w, c2 - a, a);
    }
    {
        float a = fmaf(mu_h, p2.w - p1.w, p1.w);
        float c2 = fmaf(mu_h, p4.w - p3.w, p3.w);
        o.w = fmaf(mu_w, c2 - a, a);
    }

    out[i] = o;
}

extern "C" void kernel_launch(void* const* d_in, const int* in_sizes, int n_in,
                              void* d_out, int out_size)
{
    const float*  in_tensor = (const float*)d_in[0];
    const float2* indices   = (const float2*)d_in[1];
    float4*       out       = (float4*)d_out;

    const int threads = 256;
    const int blocks  = (int)(TOTAL / threads);   // 32768
    grid_nd_sample_kernel<<<blocks, threads>>>(in_tensor, indices, out);
}

// round 4
// speedup vs baseline: 1.0267x; 1.0267x over previous
#include <cuda_runtime.h>
#include <cuda_bf16.h>
#include <cstdint>

// Grid_nd_sample: bilinear interpolation gather, ILP=2 variant.
// in_tensor: (B=16, H=128, W=128, C=256) fp32
// indices:   (B=16, P=8192, 2) fp32  -- coord0 = H axis, coord1 = W axis
// out:       (B, P, C) fp32
//
// One warp = one point. Lane l handles float4 chunks l and l+32 (two 512B
// coalesced segments per gathered row). 8 independent LDG.128 per thread for
// latency hiding; streaming stores keep the output out of L2's way.

static constexpr int B = 16;
static constexpr int H = 128;
static constexpr int W = 128;
static constexpr int C = 256;
static constexpr int P = 8192;
static constexpr int CHUNKS = C / 4;                       // 64 float4 per row
static constexpr long long TOTAL_T = (long long)B * P * 32; // 4,194,304 threads

__device__ __forceinline__ float4 bilerp4(float4 p1, float4 p2, float4 p3, float4 p4,
                                          float mh, float mw)
{
    float4 o;
    float a, c;
    a = fmaf(mh, p2.x - p1.x, p1.x); c = fmaf(mh, p4.x - p3.x, p3.x); o.x = fmaf(mw, c - a, a);
    a = fmaf(mh, p2.y - p1.y, p1.y); c = fmaf(mh, p4.y - p3.y, p3.y); o.y = fmaf(mw, c - a, a);
    a = fmaf(mh, p2.z - p1.z, p1.z); c = fmaf(mh, p4.z - p3.z, p3.z); o.z = fmaf(mw, c - a, a);
    a = fmaf(mh, p2.w - p1.w, p1.w); c = fmaf(mh, p4.w - p3.w, p3.w); o.w = fmaf(mw, c - a, a);
    return o;
}

__global__ __launch_bounds__(256, 4)
void grid_nd_sample_kernel(const float* __restrict__ in_tensor,
                           const float2* __restrict__ indices,
                           float4* __restrict__ out)
{
    unsigned int i = blockIdx.x * blockDim.x + threadIdx.x;  // < TOTAL_T
    unsigned int chunk = i & 31;          // first of two chunks (second = +32)
    unsigned int pidx  = i >> 5;          // b*P + p  (uniform across warp)
    unsigned int b     = pidx >> 13;      // P = 8192 = 2^13

    float2 ind = __ldg(&indices[pidx]);   // warp-broadcast

    float fh = floorf(ind.x);
    float fw = floorf(ind.y);
    int h0 = (int)fh;
    int w0 = (int)fw;
    int h1 = (int)ceilf(ind.x);
    int w1 = (int)ceilf(ind.y);
    float mu_h = ind.x - fh;
    float mu_w = ind.y - fw;

    const float4* base = (const float4*)in_tensor;
    unsigned int boff = b * (H * W * CHUNKS);
    unsigned int r00 = boff + (h0 * W + w0) * CHUNKS + chunk;
    unsigned int r10 = boff + (h1 * W + w0) * CHUNKS + chunk;
    unsigned int r01 = boff + (h0 * W + w1) * CHUNKS + chunk;
    unsigned int r11 = boff + (h1 * W + w1) * CHUNKS + chunk;

    // 8 independent 16B loads in flight.
    float4 p1a = __ldg(&base[r00]);
    float4 p2a = __ldg(&base[r10]);
    float4 p3a = __ldg(&base[r01]);
    float4 p4a = __ldg(&base[r11]);
    float4 p1b = __ldg(&base[r00 + 32]);
    float4 p2b = __ldg(&base[r10 + 32]);
    float4 p3b = __ldg(&base[r01 + 32]);
    float4 p4b = __ldg(&base[r11 + 32]);

    float4 oa = bilerp4(p1a, p2a, p3a, p4a, mu_h, mu_w);
    float4 ob = bilerp4(p1b, p2b, p3b, p4b, mu_h, mu_w);

    unsigned int obase = pidx * (unsigned int)CHUNKS + chunk;
    __stcs(&out[obase], oa);        // streaming store: don't pollute L2
    __stcs(&out[obase + 32], ob);
}

extern "C" void kernel_launch(void* const* d_in, const int* in_sizes, int n_in,
                              void* d_out, int out_size)
{
    const float*  in_tensor = (const float*)d_in[0];
    const float2* indices   = (const float2*)d_in[1];
    float4*       out       = (float4*)d_out;

    const int threads = 256;
    const int blocks  = (int)(TOTAL_T / threads);  // 16384
    grid_nd_sample_kernel<<<blocks, threads>>>(in_tensor, indices, out);
}